// round 11
// baseline (speedup 1.0000x reference)
#include <cuda_runtime.h>
#include <cstdint>

#define B_ 64
#define I_ 64
#define O_ 64
#define T_ 8192
#define KDIM 192      // I_*3
#define NH 64
#define MW 32
#define QD 320

#define TT 256
#define XS 264                 // x tile row stride: 264 % 32 == 8 -> conflict-free
#define CONV_THREADS 512
#define GRID 152
#define TILES_TOTAL (B_*(T_/TT))   // 2048
#define AF_FLOATS 12288        // A in fragment order: 2*24*2*32*4
#define XT_FLOATS (I_*XS)      // 16896
#define SMEM_FLOATS (AF_FLOATS + 64 + 2*XT_FLOATS)   // 46144
#define SMEM_BYTES (SMEM_FLOATS*4)                   // 184576

// -------------------- device scratch --------------------
__device__ __align__(16) float g_cwf[AF_FLOATS];  // effective A, fragment order, tf32-rounded
__device__ __align__(16) float g_bias[O_];

__device__ __forceinline__ float sigmoidf_(float x){ return 1.f/(1.f+expf(-x)); }
__device__ __forceinline__ float siluf_(float x){ return x * sigmoidf_(x); }
__device__ __forceinline__ uint32_t f2tf32(float x){
  uint32_t r; asm("cvt.rna.tf32.f32 %0, %1;" : "=r"(r) : "f"(x)); return r;
}

// ================== PREP: one block, 512 threads ==================
__global__ __launch_bounds__(512)
void prep_kernel(const float* __restrict__ grads, const float* __restrict__ q_ema,
    const float* __restrict__ W,
    const float* __restrict__ conv_w, const float* __restrict__ conv_b,
    const float* __restrict__ ctrl_w, const float* __restrict__ ctrl_b,
    const float* __restrict__ cw_w, const float* __restrict__ cw_b,
    const float* __restrict__ cb_w, const float* __restrict__ cb_b,
    const float* __restrict__ cf_w, const float* __restrict__ cf_b,
    const float* __restrict__ tau_w1, const float* __restrict__ tau_b1,
    const float* __restrict__ tau_w2, const float* __restrict__ tau_b2,
    const int* __restrict__ trigger)
{
  __shared__ float s_rep[O_*68];
  __shared__ float s_q[QD];
  __shared__ float s_red[O_];
  __shared__ float s_tau;
  __shared__ float s_att[MW];
  __shared__ int   s_idx[3];
  __shared__ float s_v[3];
  int tid = threadIdx.x;

  // rep = silu(g @ ctrl_w.T + ctrl_b): thread -> (o, 8 h's)
  {
    int o = tid >> 3, hb = (tid & 7) << 3;
    const float4* g4 = reinterpret_cast<const float4*>(grads + o*KDIM);
    float acc[8];
    #pragma unroll
    for (int hh = 0; hh < 8; ++hh) acc[hh] = ctrl_b[hb+hh];
    #pragma unroll 4
    for (int j = 0; j < 48; ++j) {
      float4 gv = __ldg(g4 + j);
      #pragma unroll
      for (int hh = 0; hh < 8; ++hh) {
        float4 wv = __ldg(reinterpret_cast<const float4*>(ctrl_w + (hb+hh)*KDIM) + j);
        acc[hh] += gv.x*wv.x + gv.y*wv.y + gv.z*wv.z + gv.w*wv.w;
      }
    }
    #pragma unroll
    for (int hh = 0; hh < 8; ++hh) s_rep[o*68 + hb + hh] = siluf_(acc[hh]);
  }
  __syncthreads();

  if (tid < 192) {                 // w head
    int o = tid/3, k = tid - 3*(tid/3);
    const float* r = s_rep + o*68;
    const float* w = cw_w + k*NH;
    float s = cw_b[k];
    #pragma unroll 8
    for (int h = 0; h < NH; ++h) s += r[h]*w[h];
    s_q[o*3+k] = s;
  } else if (tid < 256) {          // b head
    int o = tid - 192;
    const float* r = s_rep + o*68;
    float s = cb_b[0];
    #pragma unroll 8
    for (int h = 0; h < NH; ++h) s += r[h]*cb_w[h];
    s_q[192+o] = s;
  } else if (tid < 320) {          // f head
    int o = tid - 256;
    const float* r = s_rep + o*68;
    float s = cf_b[0];
    #pragma unroll 8
    for (int h = 0; h < NH; ++h) s += r[h]*cf_w[h];
    s_q[256+o] = s;
  } else if (tid < 384) {          // tau head
    int o = tid - 320;
    const float* r = s_rep + o*68;
    float acc = tau_b2[0];
    for (int j = 0; j < 16; ++j) {
      float s = tau_b1[j];
      const float* w = tau_w1 + j*NH;
      #pragma unroll 8
      for (int h = 0; h < NH; ++h) s += r[h]*w[h];
      acc += siluf_(s)*tau_w2[j];
    }
    s_red[o] = sigmoidf_(acc);
  }
  __syncthreads();
  if (tid == 0) {
    float m = 0.f;
    for (int o = 0; o < O_; ++o) m += s_red[o];
    s_tau = (m * (1.f/64.f))*0.5f + 0.5f;
  }
  __syncthreads();

  if (tid < QD) s_q[tid] = 0.85f*s_q[tid] + 0.15f*q_ema[tid];  // EMA mix
  __syncthreads();

  if (trigger[0] == 1) {
    if (tid < MW) {
      float s = 0.f;
      for (int d = 0; d < QD; ++d) s += s_q[d]*W[d*MW + tid];
      s_att[tid] = s*2.0f;   // / TEMP (0.5)
    }
    __syncthreads();
    if (tid == 0) {
      float mx = s_att[0];
      for (int m = 1; m < MW; ++m) mx = fmaxf(mx, s_att[m]);
      float sum = 0.f;
      for (int m = 0; m < MW; ++m) { float e = expf(s_att[m]-mx); s_att[m] = e; sum += e; }
      float inv = 1.f/sum;
      for (int m = 0; m < MW; ++m) s_att[m] *= inv;
      for (int j = 0; j < 3; ++j) {     // top-3, lower index wins ties (matches jax top_k)
        float best = -1e30f; int bi = 0;
        for (int m = 0; m < MW; ++m) if (s_att[m] > best) { best = s_att[m]; bi = m; }
        s_v[j] = best; s_idx[j] = bi; s_att[bi] = -1e30f;
      }
    }
    __syncthreads();
    float tau = s_tau;
    if (tid < QD) {
      float old = s_v[0]*W[tid*MW+s_idx[0]] + s_v[1]*W[tid*MW+s_idx[1]] + s_v[2]*W[tid*MW+s_idx[2]];
      s_q[tid] = tau*s_q[tid] + (1.f-tau)*old;
    }
    __syncthreads();
  }

  // emit bias + fragment-ordered A to global (kappa = k_tap*64 + i)
  if (tid < O_) g_bias[tid] = conv_b[tid]*s_q[192+tid]*s_q[256+tid];
  #pragma unroll 4
  for (int idx = tid; idx < O_*KDIM; idx += 512) {
    int o = idx / KDIM;
    int r = idx - o*KDIM;
    int i = r / 3;
    int k = r - i*3;
    float v = conv_w[idx] * s_q[o*3+k] * s_q[256+o];
    int kap = k*64 + i;
    int kk = kap >> 3, c = kap & 7;
    int t4 = c & 3, half = c >> 2;
    int wm = o >> 5, mt = (o >> 4) & 1, g = o & 7, rh = (o >> 3) & 1;
    int fi = ((((wm*24 + kk)*2 + mt)*32) + (g*4 + t4))*4 + half*2 + rh;
    g_cwf[fi] = __uint_as_float(f2tf32(v));
  }
}

// ================== CONV ==================
__device__ __forceinline__ void prefetch_tile(const float* __restrict__ x, int ti,
                                              float* __restrict__ sXb, int tid) {
  int bb = ti >> 5;
  int t0 = (ti & 31) << 8;
  const float* xb = x + (size_t)bb * (I_*T_);
  #pragma unroll
  for (int j = 0; j < 9; ++j) {
    int c = tid + j*CONV_THREADS;
    if (c < I_*66) {
      int row = c / 66;
      int jc = c - 66*row;
      int tg = t0 - 4 + jc*4;
      float* dst = sXb + row*XS + jc*4;
      if (tg >= 0 && tg <= T_-4) {
        unsigned sa = (unsigned)__cvta_generic_to_shared(dst);
        asm volatile("cp.async.cg.shared.global [%0], [%1], 16;"
                     :: "r"(sa), "l"(xb + (size_t)row*T_ + tg));
      } else {
        *reinterpret_cast<float4*>(dst) = make_float4(0.f,0.f,0.f,0.f);
      }
    }
  }
}

__global__ __launch_bounds__(CONV_THREADS, 1)
void conv_kernel(const float* __restrict__ x, float* __restrict__ out)
{
  extern __shared__ float smem[];
  float* sAf   = smem;                   // [12288] fragment-order A
  float* sBias = smem + AF_FLOATS;       // [64]
  float* sX0   = sBias + 64;             // [64][264]
  float* sX1   = sX0 + XT_FLOATS;

  int tid = threadIdx.x, bid = blockIdx.x;
  int start = (int)(((long long)bid    *TILES_TOTAL)/GRID);
  int end   = (int)(((long long)(bid+1)*TILES_TOTAL)/GRID);

  // kick off first two x-tile loads before staging A (overlap);
  // always commit two groups so the in-loop wait counts are uniform
  prefetch_tile(x, start, sX0, tid);
  asm volatile("cp.async.commit_group;");
  if (start + 1 < end) prefetch_tile(x, start+1, sX1, tid);
  asm volatile("cp.async.commit_group;");

  // stage A + bias into smem (L2-broadcast reads)
  for (int i4 = tid; i4 < AF_FLOATS/4; i4 += CONV_THREADS)
    reinterpret_cast<float4*>(sAf)[i4] = reinterpret_cast<const float4*>(g_cwf)[i4];
  if (tid < O_) sBias[tid] = g_bias[tid];
  __syncthreads();

  int wid = tid >> 5, lane = tid & 31;
  int g  = lane >> 2, t4 = lane & 3;
  int warp_m = wid & 1, warp_n = wid >> 1;     // 2 x 8 warps
  const float* sAfw = sAf + warp_m*6144 + lane*4;
  int tloc3 = warp_n*32 + g + 3;

  for (int ti = start; ti < end; ++ti) {
    float* sx = ((ti - start) & 1) ? sX1 : sX0;
    if (ti + 1 < end) { asm volatile("cp.async.wait_group 1;"); }
    else              { asm volatile("cp.async.wait_group 0;"); }
    __syncthreads();

    float c[2][4][4];
    #pragma unroll
    for (int mt = 0; mt < 2; ++mt)
      #pragma unroll
      for (int nt = 0; nt < 4; ++nt)
        { c[mt][nt][0]=0.f; c[mt][nt][1]=0.f; c[mt][nt][2]=0.f; c[mt][nt][3]=0.f; }

    const float* pB = sx + t4*XS + tloc3;

    #pragma unroll
    for (int kk = 0; kk < 24; ++kk) {
      const int ktap = kk >> 3;   // compile-time after unroll
      const int ic   = kk & 7;
      float4 a0 = *reinterpret_cast<const float4*>(sAfw + (kk*2+0)*128);
      float4 a1 = *reinterpret_cast<const float4*>(sAfw + (kk*2+1)*128);
      const float* pb = pB + ic*(8*XS) + ktap;
      uint32_t b0[4], b1[4];
      #pragma unroll
      for (int nt = 0; nt < 4; ++nt) {
        b0[nt] = f2tf32(pb[nt*8]);            // banks 8*t4+g: conflict-free
        b1[nt] = f2tf32(pb[4*XS + nt*8]);
      }
      #pragma unroll
      for (int nt = 0; nt < 4; ++nt) {
        asm("mma.sync.aligned.m16n8k8.row.col.f32.tf32.tf32.f32 "
            "{%0,%1,%2,%3}, {%4,%5,%6,%7}, {%8,%9}, {%0,%1,%2,%3};"
            : "+f"(c[0][nt][0]), "+f"(c[0][nt][1]), "+f"(c[0][nt][2]), "+f"(c[0][nt][3])
            : "r"(__float_as_uint(a0.x)), "r"(__float_as_uint(a0.y)),
              "r"(__float_as_uint(a0.z)), "r"(__float_as_uint(a0.w)),
              "r"(b0[nt]), "r"(b1[nt]));
        asm("mma.sync.aligned.m16n8k8.row.col.f32.tf32.tf32.f32 "
            "{%0,%1,%2,%3}, {%4,%5,%6,%7}, {%8,%9}, {%0,%1,%2,%3};"
            : "+f"(c[1][nt][0]), "+f"(c[1][nt][1]), "+f"(c[1][nt][2]), "+f"(c[1][nt][3])
            : "r"(__float_as_uint(a1.x)), "r"(__float_as_uint(a1.y)),
              "r"(__float_as_uint(a1.z)), "r"(__float_as_uint(a1.w)),
              "r"(b0[nt]), "r"(b1[nt]));
      }
    }
    __syncthreads();  // done reading sx

    if (ti + 2 < end) {
      prefetch_tile(x, ti+2, sx, tid);
      asm volatile("cp.async.commit_group;");
    }

    // epilogue
    int bb = ti >> 5;
    int t0 = (ti & 31) << 8;
    float* outb = out + (size_t)bb*(O_*T_) + t0 + warp_n*32 + t4*2;
    #pragma unroll
    for (int mt = 0; mt < 2; ++mt) {
      int o0 = warp_m*32 + mt*16 + g;
      float bv0 = sBias[o0], bv1 = sBias[o0+8];
      float* p0 = outb + (size_t)o0*T_;
      float* p1 = p0 + (size_t)8*T_;
      #pragma unroll
      for (int nt = 0; nt < 4; ++nt) {
        *reinterpret_cast<float2*>(p0 + nt*8) = make_float2(c[mt][nt][0]+bv0, c[mt][nt][1]+bv0);
        *reinterpret_cast<float2*>(p1 + nt*8) = make_float2(c[mt][nt][2]+bv1, c[mt][nt][3]+bv1);
      }
    }
  }
}

// -------------------- launch --------------------
extern "C" void kernel_launch(void* const* d_in, const int* in_sizes, int n_in,
                              void* d_out, int out_size) {
  const float* x      = (const float*)d_in[0];
  const float* grads  = (const float*)d_in[1];
  const float* q_ema  = (const float*)d_in[2];
  const float* W      = (const float*)d_in[3];
  const float* conv_w = (const float*)d_in[4];
  const float* conv_b = (const float*)d_in[5];
  const float* ctrl_w = (const float*)d_in[6];
  const float* ctrl_b = (const float*)d_in[7];
  const float* cw_w   = (const float*)d_in[8];
  const float* cw_b   = (const float*)d_in[9];
  const float* cb_w   = (const float*)d_in[10];
  const float* cb_b   = (const float*)d_in[11];
  const float* cf_w   = (const float*)d_in[12];
  const float* cf_b   = (const float*)d_in[13];
  const float* tau_w1 = (const float*)d_in[14];
  const float* tau_b1 = (const float*)d_in[15];
  const float* tau_w2 = (const float*)d_in[16];
  const float* tau_b2 = (const float*)d_in[17];
  const int*   trig   = (const int*)d_in[18];
  float* out = (float*)d_out;

  static bool attr_set = false;
  if (!attr_set) {
    cudaFuncSetAttribute(conv_kernel, cudaFuncAttributeMaxDynamicSharedMemorySize, SMEM_BYTES);
    attr_set = true;
  }

  prep_kernel<<<1, 512>>>(grads, q_ema, W, conv_w, conv_b, ctrl_w, ctrl_b,
                          cw_w, cw_b, cb_w, cb_b, cf_w, cf_b,
                          tau_w1, tau_b1, tau_w2, tau_b2, trig);
  conv_kernel<<<GRID, CONV_THREADS, SMEM_BYTES>>>(x, out);
}

// round 13
// speedup vs baseline: 1.6520x; 1.6520x over previous
#include <cuda_runtime.h>
#include <cstdint>

#define B_ 64
#define I_ 64
#define O_ 64
#define T_ 8192
#define KDIM 192      // I_*3
#define NH 64
#define MW 32
#define QD 320

#define TT 256
#define XS 264                 // x tile row stride: 264 % 32 == 8 -> conflict-free
#define CONV_THREADS 512
#define GRID 152
#define TILES_TOTAL (B_*(T_/TT))   // 2048
#define AF_FLOATS 12288        // A fragment region; also exactly 64*192 for ctrl_w staging
#define XT_FLOATS (I_*XS)      // 16896
#define SMEM_FLOATS (AF_FLOATS + 64 + 2*XT_FLOATS)   // 46144
#define SMEM_BYTES (SMEM_FLOATS*4)                   // 184576

__device__ __forceinline__ float sigmoidf_(float x){ return 1.f/(1.f+expf(-x)); }
__device__ __forceinline__ float siluf_(float x){ return x * sigmoidf_(x); }
__device__ __forceinline__ uint32_t f2tf32(float x){
  uint32_t r; asm("cvt.rna.tf32.f32 %0, %1;" : "=r"(r) : "f"(x)); return r;
}

__device__ __forceinline__ void prefetch_tile(const float* __restrict__ x, int ti,
                                              float* __restrict__ sXb, int tid) {
  int bb = ti >> 5;
  int t0 = (ti & 31) << 8;
  const float* xb = x + (size_t)bb * (I_*T_);
  #pragma unroll
  for (int j = 0; j < 9; ++j) {
    int c = tid + j*CONV_THREADS;
    if (c < I_*66) {
      int row = c / 66;
      int jc = c - 66*row;
      int tg = t0 - 4 + jc*4;
      float* dst = sXb + row*XS + jc*4;
      if (tg >= 0 && tg <= T_-4) {
        unsigned sa = (unsigned)__cvta_generic_to_shared(dst);
        asm volatile("cp.async.cg.shared.global [%0], [%1], 16;"
                     :: "r"(sa), "l"(xb + (size_t)row*T_ + tg));
      } else {
        *reinterpret_cast<float4*>(dst) = make_float4(0.f,0.f,0.f,0.f);
      }
    }
  }
}

__global__ __launch_bounds__(CONV_THREADS, 1)
void fused_kernel(const float* __restrict__ x, float* __restrict__ out,
    const float* __restrict__ grads, const float* __restrict__ q_ema,
    const float* __restrict__ W,
    const float* __restrict__ conv_w, const float* __restrict__ conv_b,
    const float* __restrict__ ctrl_w, const float* __restrict__ ctrl_b,
    const float* __restrict__ cw_w, const float* __restrict__ cw_b,
    const float* __restrict__ cb_w, const float* __restrict__ cb_b,
    const float* __restrict__ cf_w, const float* __restrict__ cf_b,
    const float* __restrict__ tau_w1, const float* __restrict__ tau_b1,
    const float* __restrict__ tau_w2, const float* __restrict__ tau_b2,
    const int* __restrict__ trigger)
{
  extern __shared__ float smem[];
  float* sAf   = smem;                   // ctrl_w staging (prep) -> A fragments (conv)
  float* sBias = smem + AF_FLOATS;       // [64]
  float* sX0   = sBias + 64;             // [64][264]
  float* sX1   = sX0 + XT_FLOATS;

  __shared__ float s_rep[O_*68];
  __shared__ float s_q[QD];
  __shared__ float s_red[O_];
  __shared__ float s_tau;
  __shared__ float s_att[MW];
  __shared__ int   s_idx[3];
  __shared__ float s_v[3];

  int tid = threadIdx.x, bid = blockIdx.x;
  int start = (int)(((long long)bid    *TILES_TOTAL)/GRID);
  int end   = (int)(((long long)(bid+1)*TILES_TOTAL)/GRID);

  // kick off first two x-tile loads; their DRAM latency overlaps all of prep
  prefetch_tile(x, start, sX0, tid);
  asm volatile("cp.async.commit_group;");
  if (start + 1 < end) prefetch_tile(x, start+1, sX1, tid);
  asm volatile("cp.async.commit_group;");

  // ---- stage ctrl_w into sAf, coalesced, with per-row rotation swizzle ----
  // row h's float4 #j4 stored at slot (j4 + (h>>3)&7) % 48  -> conflict-free reads
  for (int i4 = tid; i4 < NH*48; i4 += CONV_THREADS) {
    int h = i4 / 48, j4 = i4 - h*48;
    int slot = j4 + ((h >> 3) & 7); if (slot >= 48) slot -= 48;
    reinterpret_cast<float4*>(sAf)[h*48 + slot] = reinterpret_cast<const float4*>(ctrl_w)[i4];
  }
  __syncthreads();

  // ---- rep = silu(g @ ctrl_w.T + ctrl_b): thread -> (o, 8 h's) ----
  {
    int o = tid >> 3, hb = (tid & 7) << 3;
    int rot = tid & 7;                      // == (h>>3)&7 for all 8 rows of this thread
    const float4* g4 = reinterpret_cast<const float4*>(grads + o*KDIM);
    float acc[8];
    #pragma unroll
    for (int hh = 0; hh < 8; ++hh) acc[hh] = ctrl_b[hb+hh];
    #pragma unroll 4
    for (int j4 = 0; j4 < 48; ++j4) {
      float4 gv = __ldg(g4 + j4);
      int slot = j4 + rot; if (slot >= 48) slot -= 48;
      #pragma unroll
      for (int hh = 0; hh < 8; ++hh) {
        float4 wv = reinterpret_cast<const float4*>(sAf)[(hb+hh)*48 + slot];
        acc[hh] += gv.x*wv.x + gv.y*wv.y + gv.z*wv.z + gv.w*wv.w;
      }
    }
    #pragma unroll
    for (int hh = 0; hh < 8; ++hh) s_rep[o*68 + hb + hh] = siluf_(acc[hh]);
  }
  __syncthreads();

  // ---- heads ----
  if (tid < 192) {                 // w head
    int o = tid/3, k = tid - 3*(tid/3);
    const float* r = s_rep + o*68;
    const float* w = cw_w + k*NH;
    float s = cw_b[k];
    #pragma unroll 8
    for (int h = 0; h < NH; ++h) s += r[h]*w[h];
    s_q[o*3+k] = s;
  } else if (tid < 256) {          // b head
    int o = tid - 192;
    const float* r = s_rep + o*68;
    float s = cb_b[0];
    #pragma unroll 8
    for (int h = 0; h < NH; ++h) s += r[h]*cb_w[h];
    s_q[192+o] = s;
  } else if (tid < 320) {          // f head
    int o = tid - 256;
    const float* r = s_rep + o*68;
    float s = cf_b[0];
    #pragma unroll 8
    for (int h = 0; h < NH; ++h) s += r[h]*cf_w[h];
    s_q[256+o] = s;
  } else if (tid < 384) {          // tau head
    int o = tid - 320;
    const float* r = s_rep + o*68;
    float acc = tau_b2[0];
    for (int j = 0; j < 16; ++j) {
      float s = tau_b1[j];
      const float* w = tau_w1 + j*NH;
      #pragma unroll 8
      for (int h = 0; h < NH; ++h) s += r[h]*w[h];
      acc += siluf_(s)*tau_w2[j];
    }
    s_red[o] = sigmoidf_(acc);
  }
  __syncthreads();
  if (tid == 0) {
    float m = 0.f;
    for (int o = 0; o < O_; ++o) m += s_red[o];
    s_tau = (m * (1.f/64.f))*0.5f + 0.5f;
  }
  __syncthreads();

  if (tid < QD) s_q[tid] = 0.85f*s_q[tid] + 0.15f*q_ema[tid];  // EMA mix
  __syncthreads();

  if (trigger[0] == 1) {
    if (tid < MW) {
      float s = 0.f;
      for (int d = 0; d < QD; ++d) s += s_q[d]*W[d*MW + tid];
      s_att[tid] = s*2.0f;   // / TEMP (0.5)
    }
    __syncthreads();
    if (tid == 0) {
      float mx = s_att[0];
      for (int m = 1; m < MW; ++m) mx = fmaxf(mx, s_att[m]);
      float sum = 0.f;
      for (int m = 0; m < MW; ++m) { float e = expf(s_att[m]-mx); s_att[m] = e; sum += e; }
      float inv = 1.f/sum;
      for (int m = 0; m < MW; ++m) s_att[m] *= inv;
      for (int j = 0; j < 3; ++j) {     // top-3, lower index wins ties (matches jax top_k)
        float best = -1e30f; int bi = 0;
        for (int m = 0; m < MW; ++m) if (s_att[m] > best) { best = s_att[m]; bi = m; }
        s_v[j] = best; s_idx[j] = bi; s_att[bi] = -1e30f;
      }
    }
    __syncthreads();
    float tau = s_tau;
    if (tid < QD) {
      float old = s_v[0]*W[tid*MW+s_idx[0]] + s_v[1]*W[tid*MW+s_idx[1]] + s_v[2]*W[tid*MW+s_idx[2]];
      s_q[tid] = tau*s_q[tid] + (1.f-tau)*old;
    }
    __syncthreads();
  }

  // ---- emit bias + fragment-ordered A into sAf (overwrites ctrl_w staging) ----
  if (tid < O_) sBias[tid] = conv_b[tid]*s_q[192+tid]*s_q[256+tid];
  #pragma unroll 4
  for (int idx = tid; idx < O_*KDIM; idx += CONV_THREADS) {
    int o = idx / KDIM;
    int r = idx - o*KDIM;
    int i = r / 3;
    int k = r - i*3;
    float v = conv_w[idx] * s_q[o*3+k] * s_q[256+o];
    int kap = k*64 + i;
    int kk = kap >> 3, c = kap & 7;
    int t4 = c & 3, half = c >> 2;
    int wm = o >> 5, mt = (o >> 4) & 1, g = o & 7, rh = (o >> 3) & 1;
    int fi = ((((wm*24 + kk)*2 + mt)*32) + (g*4 + t4))*4 + half*2 + rh;
    sAf[fi] = __uint_as_float(f2tf32(v));
  }
  __syncthreads();

  // ================== CONV mainloop (verified) ==================
  int wid = tid >> 5, lane = tid & 31;
  int g  = lane >> 2, t4 = lane & 3;
  int warp_m = wid & 1, warp_n = wid >> 1;     // 2 x 8 warps
  const float* sAfw = sAf + warp_m*6144 + lane*4;
  int tloc3 = warp_n*32 + g + 3;

  for (int ti = start; ti < end; ++ti) {
    float* sx = ((ti - start) & 1) ? sX1 : sX0;
    if (ti + 1 < end) { asm volatile("cp.async.wait_group 1;"); }
    else              { asm volatile("cp.async.wait_group 0;"); }
    __syncthreads();

    float c[2][4][4];
    #pragma unroll
    for (int mt = 0; mt < 2; ++mt)
      #pragma unroll
      for (int nt = 0; nt < 4; ++nt)
        { c[mt][nt][0]=0.f; c[mt][nt][1]=0.f; c[mt][nt][2]=0.f; c[mt][nt][3]=0.f; }

    const float* pB = sx + t4*XS + tloc3;

    #pragma unroll
    for (int kk = 0; kk < 24; ++kk) {
      const int ktap = kk >> 3;   // compile-time after unroll
      const int ic   = kk & 7;
      float4 a0 = *reinterpret_cast<const float4*>(sAfw + (kk*2+0)*128);
      float4 a1 = *reinterpret_cast<const float4*>(sAfw + (kk*2+1)*128);
      const float* pb = pB + ic*(8*XS) + ktap;
      uint32_t b0[4], b1[4];
      #pragma unroll
      for (int nt = 0; nt < 4; ++nt) {
        b0[nt] = f2tf32(pb[nt*8]);            // banks 8*t4+g: conflict-free
        b1[nt] = f2tf32(pb[4*XS + nt*8]);
      }
      #pragma unroll
      for (int nt = 0; nt < 4; ++nt) {
        asm("mma.sync.aligned.m16n8k8.row.col.f32.tf32.tf32.f32 "
            "{%0,%1,%2,%3}, {%4,%5,%6,%7}, {%8,%9}, {%0,%1,%2,%3};"
            : "+f"(c[0][nt][0]), "+f"(c[0][nt][1]), "+f"(c[0][nt][2]), "+f"(c[0][nt][3])
            : "r"(__float_as_uint(a0.x)), "r"(__float_as_uint(a0.y)),
              "r"(__float_as_uint(a0.z)), "r"(__float_as_uint(a0.w)),
              "r"(b0[nt]), "r"(b1[nt]));
        asm("mma.sync.aligned.m16n8k8.row.col.f32.tf32.tf32.f32 "
            "{%0,%1,%2,%3}, {%4,%5,%6,%7}, {%8,%9}, {%0,%1,%2,%3};"
            : "+f"(c[1][nt][0]), "+f"(c[1][nt][1]), "+f"(c[1][nt][2]), "+f"(c[1][nt][3])
            : "r"(__float_as_uint(a1.x)), "r"(__float_as_uint(a1.y)),
              "r"(__float_as_uint(a1.z)), "r"(__float_as_uint(a1.w)),
              "r"(b0[nt]), "r"(b1[nt]));
      }
    }
    __syncthreads();  // done reading sx

    if (ti + 2 < end) {
      prefetch_tile(x, ti+2, sx, tid);
      asm volatile("cp.async.commit_group;");
    }

    // epilogue
    int bb = ti >> 5;
    int t0 = (ti & 31) << 8;
    float* outb = out + (size_t)bb*(O_*T_) + t0 + warp_n*32 + t4*2;
    #pragma unroll
    for (int mt = 0; mt < 2; ++mt) {
      int o0 = warp_m*32 + mt*16 + g;
      float bv0 = sBias[o0], bv1 = sBias[o0+8];
      float* p0 = outb + (size_t)o0*T_;
      float* p1 = p0 + (size_t)8*T_;
      #pragma unroll
      for (int nt = 0; nt < 4; ++nt) {
        *reinterpret_cast<float2*>(p0 + nt*8) = make_float2(c[mt][nt][0]+bv0, c[mt][nt][1]+bv0);
        *reinterpret_cast<float2*>(p1 + nt*8) = make_float2(c[mt][nt][2]+bv1, c[mt][nt][3]+bv1);
      }
    }
  }
}

// -------------------- launch --------------------
extern "C" void kernel_launch(void* const* d_in, const int* in_sizes, int n_in,
                              void* d_out, int out_size) {
  const float* x      = (const float*)d_in[0];
  const float* grads  = (const float*)d_in[1];
  const float* q_ema  = (const float*)d_in[2];
  const float* W      = (const float*)d_in[3];
  const float* conv_w = (const float*)d_in[4];
  const float* conv_b = (const float*)d_in[5];
  const float* ctrl_w = (const float*)d_in[6];
  const float* ctrl_b = (const float*)d_in[7];
  const float* cw_w   = (const float*)d_in[8];
  const float* cw_b   = (const float*)d_in[9];
  const float* cb_w   = (const float*)d_in[10];
  const float* cb_b   = (const float*)d_in[11];
  const float* cf_w   = (const float*)d_in[12];
  const float* cf_b   = (const float*)d_in[13];
  const float* tau_w1 = (const float*)d_in[14];
  const float* tau_b1 = (const float*)d_in[15];
  const float* tau_w2 = (const float*)d_in[16];
  const float* tau_b2 = (const float*)d_in[17];
  const int*   trig   = (const int*)d_in[18];
  float* out = (float*)d_out;

  cudaFuncSetAttribute(fused_kernel, cudaFuncAttributeMaxDynamicSharedMemorySize, SMEM_BYTES);
  fused_kernel<<<GRID, CONV_THREADS, SMEM_BYTES>>>(x, out, grads, q_ema, W, conv_w, conv_b,
      ctrl_w, ctrl_b, cw_w, cw_b, cb_w, cb_b, cf_w, cf_b,
      tau_w1, tau_b1, tau_w2, tau_b2, trig);
}